// round 3
// baseline (speedup 1.0000x reference)
#include <cuda_runtime.h>

// ---------------------------------------------------------------------------
// EnhancedQuanvolution: x(65536,1,28,28) -> 2x2 patches -> cumprod(cos)
// -> feat(784) @ W^T(784,10) + b -> log_softmax -> out(65536,10)
//
// Round 3: weights moved to __constant__ memory (warp-uniform index -> LDCU
// uniform path, no shared-memory crossbar traffic). Image data still staged
// coalesced via cp.async into shared, double-buffered 2-row chunks,
// one image per thread, block=448, grid=147.
// ---------------------------------------------------------------------------

__constant__ float cW[7840];   // W[10][784]; float4 at (o*196+p) = W[o][4p..4p+3]
__constant__ float cB[10];

__device__ __forceinline__ unsigned long long f32x2_fma(unsigned long long a,
                                                        unsigned long long b,
                                                        unsigned long long c) {
    unsigned long long d;
    asm("fma.rn.f32x2 %0, %1, %2, %3;" : "=l"(d) : "l"(a), "l"(b), "l"(c));
    return d;
}

__device__ __forceinline__ unsigned long long pack2(float lo, float hi) {
    unsigned long long d;
    asm("mov.b64 %0, {%1, %2};" : "=l"(d) : "f"(lo), "f"(hi));
    return d;
}

__device__ __forceinline__ void unpack2(unsigned long long v, float& lo, float& hi) {
    asm("mov.b64 {%0, %1}, %2;" : "=f"(lo), "=f"(hi) : "l"(v));
}

__device__ __forceinline__ void cp_async16(void* dst_smem, const void* src_gmem) {
    unsigned sd = (unsigned)__cvta_generic_to_shared(dst_smem);
    asm volatile("cp.async.cg.shared.global [%0], [%1], 16;"
                 :: "r"(sd), "l"(src_gmem) : "memory");
}

static constexpr int THREADS       = 448;
static constexpr int IMG_PER_BLOCK = 448;
static constexpr int NCHUNK        = 14;                   // 14 patch-rows
static constexpr int PLANE_FLOATS  = IMG_PER_BLOCK * 28;   // 12544 (50176 B)
static constexpr int SLOT_FLOATS   = 2 * PLANE_FLOATS;     // 25088 (100352 B)
static constexpr int STAGE_FLOATS  = 2 * SLOT_FLOATS;      // 50176 (200704 B)
static constexpr int SMEM_BYTES    = STAGE_FLOATS * 4;     // 200704

// Stage chunk c (image rows 2c, 2c+1) for this block into slot.
__device__ __forceinline__ void stage_chunk(const float* __restrict__ x,
                                            float* __restrict__ sm,
                                            int base, int batch,
                                            int slot, int c, int tid) {
    float* s0 = sm + slot * SLOT_FLOATS;
#pragma unroll
    for (int k = 0; k < 14; k++) {
        int n = tid + THREADS * k;        // 0 .. 6271  (448 imgs * 14 float4)
        int img = n / 14;
        int j = n % 14;                   // float4 index within 224B chunk
        int gimg = base + img;
        if (gimg < batch) {
            const char* src = (const char*)(x + (size_t)gimg * 784 + c * 56) + j * 16;
            int jj = (j < 7) ? j : (j - 7);
            float* dst = s0 + ((j < 7) ? 0 : PLANE_FLOATS) + img * 28 + jj * 4;
            cp_async16(dst, src);
        }
    }
    asm volatile("cp.async.commit_group;" ::: "memory");
}

__global__ __launch_bounds__(THREADS, 1)
void quanv_kernel(const float* __restrict__ x,
                  float* __restrict__ out,
                  int batch) {
    extern __shared__ float sm[];

    const int tid = threadIdx.x;
    const int base = blockIdx.x * IMG_PER_BLOCK;

    // ---- prologue: stage chunks 0,1 -----------------------------------------
    stage_chunk(x, sm, base, batch, 0, 0, tid);
    stage_chunk(x, sm, base, batch, 1, 1, tid);

    const bool img_ok = (base + tid) < batch;
    const float4* __restrict__ cW4 = (const float4*)cW;

    unsigned long long acc[10];
#pragma unroll
    for (int o = 0; o < 10; o++) acc[o] = 0ULL;

#pragma unroll 1
    for (int c = 0; c < NCHUNK; c++) {
        if (c < NCHUNK - 1) asm volatile("cp.async.wait_group 1;" ::: "memory");
        else                asm volatile("cp.async.wait_group 0;" ::: "memory");
        __syncthreads();

        if (img_ok) {
            const float4* p0 = (const float4*)(sm + (c & 1) * SLOT_FLOATS + tid * 28);
            const float4* p1 = (const float4*)(sm + (c & 1) * SLOT_FLOATS + PLANE_FLOATS + tid * 28);
#pragma unroll
            for (int v = 0; v < 7; v++) {
                float4 q0 = p0[v];   // row 2c, pixels 4v..4v+3
                float4 q1 = p1[v];   // row 2c+1

                // patch (c, 2v): q0.x q0.y / q1.x q1.y
                {
                    int patch = c * 14 + 2 * v;
                    float f0 = __cosf(q0.x);
                    float f1 = f0 * __cosf(q0.y);
                    float f2 = f1 * __cosf(q1.x);
                    float f3 = f2 * __cosf(q1.y);
                    unsigned long long fA = pack2(f0, f1);
                    unsigned long long fB = pack2(f2, f3);
#pragma unroll
                    for (int o = 0; o < 10; o++) {
                        float4 w = cW4[o * 196 + patch];   // warp-uniform -> LDCU
                        acc[o] = f32x2_fma(fA, pack2(w.x, w.y), acc[o]);
                        acc[o] = f32x2_fma(fB, pack2(w.z, w.w), acc[o]);
                    }
                }
                // patch (c, 2v+1): q0.z q0.w / q1.z q1.w
                {
                    int patch = c * 14 + 2 * v + 1;
                    float f0 = __cosf(q0.z);
                    float f1 = f0 * __cosf(q0.w);
                    float f2 = f1 * __cosf(q1.z);
                    float f3 = f2 * __cosf(q1.w);
                    unsigned long long fA = pack2(f0, f1);
                    unsigned long long fB = pack2(f2, f3);
#pragma unroll
                    for (int o = 0; o < 10; o++) {
                        float4 w = cW4[o * 196 + patch];
                        acc[o] = f32x2_fma(fA, pack2(w.x, w.y), acc[o]);
                        acc[o] = f32x2_fma(fB, pack2(w.z, w.w), acc[o]);
                    }
                }
            }
        }
        __syncthreads();

        if (c + 2 < NCHUNK) stage_chunk(x, sm, base, batch, c & 1, c + 2, tid);
    }

    if (!img_ok) return;

    // ---- logits + log_softmax ------------------------------------------------
    float lg[10];
    float m = -1e30f;
#pragma unroll
    for (int o = 0; o < 10; o++) {
        float lo, hi;
        unpack2(acc[o], lo, hi);
        lg[o] = lo + hi + cB[o];
        m = fmaxf(m, lg[o]);
    }
    float s = 0.f;
#pragma unroll
    for (int o = 0; o < 10; o++) s += __expf(lg[o] - m);
    float lse = m + __logf(s);

    float* op = out + (size_t)(base + tid) * 10;
#pragma unroll
    for (int o = 0; o < 10; o += 2) {
        *(float2*)(op + o) = make_float2(lg[o] - lse, lg[o + 1] - lse);
    }
}

extern "C" void kernel_launch(void* const* d_in, const int* in_sizes, int n_in,
                              void* d_out, int out_size) {
    const float* x = (const float*)d_in[0];   // (B,1,28,28) fp32
    const float* W = (const float*)d_in[1];   // (10,784)    fp32
    const float* b = (const float*)d_in[2];   // (10,)       fp32
    float* out = (float*)d_out;               // (B,10)      fp32

    int batch = in_sizes[0] / 784;
    int grid = (batch + IMG_PER_BLOCK - 1) / IMG_PER_BLOCK;

    // D2D copies into constant memory — async, graph-capturable memcpy nodes.
    cudaMemcpyToSymbolAsync(cW, W, 7840 * sizeof(float), 0,
                            cudaMemcpyDeviceToDevice, 0);
    cudaMemcpyToSymbolAsync(cB, b, 10 * sizeof(float), 0,
                            cudaMemcpyDeviceToDevice, 0);

    cudaFuncSetAttribute(quanv_kernel,
                         cudaFuncAttributeMaxDynamicSharedMemorySize, SMEM_BYTES);
    quanv_kernel<<<grid, THREADS, SMEM_BYTES>>>(x, out, batch);
}

// round 4
// speedup vs baseline: 1.5955x; 1.5955x over previous
#include <cuda_runtime.h>

// ---------------------------------------------------------------------------
// EnhancedQuanvolution: x(65536,1,28,28) -> 2x2 patches -> cumprod(cos)
// -> feat(784) @ W^T(784,10) + b -> log_softmax -> out(65536,10)
//
// Round 4: warp-private double-buffered cp.async pipeline (no block barriers
// in the main loop). Each warp owns 32 images + a private 2x7168B stage
// buffer; chunks of 2 image rows are staged coalesced and consumed from a
// conflict-free two-plane layout (112B image stride). Weights pre-packed as
// f32x2 pairs in shared (broadcast LDS), GEMV via packed fma.rn.f32x2.
// block=448 (14 warps), grid=147 (one wave on 148 SMs).
// ---------------------------------------------------------------------------

__device__ __forceinline__ unsigned long long f32x2_fma(unsigned long long a,
                                                        unsigned long long b,
                                                        unsigned long long c) {
    unsigned long long d;
    asm("fma.rn.f32x2 %0, %1, %2, %3;" : "=l"(d) : "l"(a), "l"(b), "l"(c));
    return d;
}

__device__ __forceinline__ unsigned long long pack2(float lo, float hi) {
    unsigned long long d;
    asm("mov.b64 %0, {%1, %2};" : "=l"(d) : "f"(lo), "f"(hi));
    return d;
}

__device__ __forceinline__ void unpack2(unsigned long long v, float& lo, float& hi) {
    asm("mov.b64 {%0, %1}, %2;" : "=f"(lo), "=f"(hi) : "l"(v));
}

__device__ __forceinline__ void cp_async16(void* dst_smem, const void* src_gmem) {
    unsigned sd = (unsigned)__cvta_generic_to_shared(dst_smem);
    asm volatile("cp.async.cg.shared.global [%0], [%1], 16;"
                 :: "r"(sd), "l"(src_gmem) : "memory");
}

static constexpr int THREADS       = 448;
static constexpr int WARPS         = 14;
static constexpr int IMG_PER_BLOCK = 448;
static constexpr int NCHUNK        = 14;     // 14 patch-rows (2 image rows each)
static constexpr int SLOT_FLOATS   = 2 * 32 * 28;              // 1792 floats (7168B): two planes
static constexpr int WARP_FLOATS   = 2 * SLOT_FLOATS;          // double buffer
static constexpr int STAGE_FLOATS  = WARPS * WARP_FLOATS;      // 50176 floats (200704B)
static constexpr int WS_U64        = 196 * 20;                 // 3920 (31360B)
static constexpr int SMEM_BYTES    = STAGE_FLOATS * 4 + WS_U64 * 8 + 40; // 232104

// Stage chunk c (image rows 2c,2c+1) for this warp's 32 images into slotbase.
__device__ __forceinline__ void stage_chunk(const float* __restrict__ x,
                                            float* __restrict__ slotbase,
                                            int gbase, int batch,
                                            int c, int lane) {
#pragma unroll
    for (int k = 0; k < 14; k++) {
        int n = lane + 32 * k;           // 0..447 = 32 imgs * 14 float4
        int img = n / 14;
        int j = n - img * 14;            // float4 index within 224B chunk
        int gimg = gbase + img;
        if (gimg < batch) {
            const float* src = x + (size_t)gimg * 784 + c * 56 + j * 4;
            float* dst = slotbase + ((j < 7) ? 0 : 896) + img * 28
                       + ((j < 7) ? j : (j - 7)) * 4;
            cp_async16(dst, src);
        }
    }
    asm volatile("cp.async.commit_group;" ::: "memory");
}

__global__ __launch_bounds__(THREADS, 1)
void quanv_kernel(const float* __restrict__ x,
                  const float* __restrict__ W,
                  const float* __restrict__ bias,
                  float* __restrict__ out,
                  int batch) {
    extern __shared__ float sm[];
    unsigned long long* ws = (unsigned long long*)(sm + STAGE_FLOATS);
    float* bsh = (float*)(ws + WS_U64);

    const int tid  = threadIdx.x;
    const int lane = tid & 31;
    const int warp = tid >> 5;

    // ---- pack weights: per patch p, per output o:
    //      {W[o][4p+0],W[o][4p+1]}, {W[o][4p+2],W[o][4p+3]} -------------------
    for (int n = tid; n < WS_U64; n += THREADS) {
        int patch = n / 20;
        int t = n % 20;
        int o = t >> 1;
        int pr = t & 1;
        int f = patch * 4 + pr * 2;
        ws[n] = pack2(W[o * 784 + f], W[o * 784 + f + 1]);
    }
    if (tid < 10) bsh[tid] = bias[tid];
    __syncthreads();   // only block-wide barrier

    const int gbase = blockIdx.x * IMG_PER_BLOCK + warp * 32;  // this warp's images
    float* wbuf = sm + warp * WARP_FLOATS;                     // private double buffer
    const bool img_ok = (gbase + lane) < batch;

    // ---- prologue: stage chunks 0,1 ------------------------------------------
    stage_chunk(x, wbuf, gbase, batch, 0, lane);
    stage_chunk(x, wbuf + SLOT_FLOATS, gbase, batch, 1, lane);

    unsigned long long acc[10];
#pragma unroll
    for (int o = 0; o < 10; o++) acc[o] = 0ULL;

#pragma unroll 1
    for (int c = 0; c < NCHUNK; c++) {
        if (c < NCHUNK - 1) asm volatile("cp.async.wait_group 1;" ::: "memory");
        else                asm volatile("cp.async.wait_group 0;" ::: "memory");
        __syncwarp();   // other lanes' copies into this slot are also complete

        float* slot = wbuf + (c & 1) * SLOT_FLOATS;
        if (img_ok) {
            const float4* p0 = (const float4*)(slot + lane * 28);         // row 2c
            const float4* p1 = (const float4*)(slot + 896 + lane * 28);   // row 2c+1
#pragma unroll
            for (int v = 0; v < 7; v++) {
                float4 q0 = p0[v];
                float4 q1 = p1[v];

                // patch (c, 2v): q0.x q0.y / q1.x q1.y
                {
                    int patch = c * 14 + 2 * v;
                    float f0 = __cosf(q0.x);
                    float f1 = f0 * __cosf(q0.y);
                    float f2 = f1 * __cosf(q1.x);
                    float f3 = f2 * __cosf(q1.y);
                    unsigned long long fA = pack2(f0, f1);
                    unsigned long long fB = pack2(f2, f3);
                    const ulonglong2* wp = (const ulonglong2*)&ws[patch * 20];
#pragma unroll
                    for (int o = 0; o < 10; o++) {
                        ulonglong2 w = wp[o];
                        acc[o] = f32x2_fma(fA, w.x, acc[o]);
                        acc[o] = f32x2_fma(fB, w.y, acc[o]);
                    }
                }
                // patch (c, 2v+1): q0.z q0.w / q1.z q1.w
                {
                    int patch = c * 14 + 2 * v + 1;
                    float f0 = __cosf(q0.z);
                    float f1 = f0 * __cosf(q0.w);
                    float f2 = f1 * __cosf(q1.z);
                    float f3 = f2 * __cosf(q1.w);
                    unsigned long long fA = pack2(f0, f1);
                    unsigned long long fB = pack2(f2, f3);
                    const ulonglong2* wp = (const ulonglong2*)&ws[patch * 20];
#pragma unroll
                    for (int o = 0; o < 10; o++) {
                        ulonglong2 w = wp[o];
                        acc[o] = f32x2_fma(fA, w.x, acc[o]);
                        acc[o] = f32x2_fma(fB, w.y, acc[o]);
                    }
                }
            }
        }
        __syncwarp();   // all lanes done reading this slot before overwrite

        if (c + 2 < NCHUNK) stage_chunk(x, slot, gbase, batch, c + 2, lane);
    }

    if (!img_ok) return;

    // ---- logits + log_softmax -------------------------------------------------
    float lg[10];
    float m = -1e30f;
#pragma unroll
    for (int o = 0; o < 10; o++) {
        float lo, hi;
        unpack2(acc[o], lo, hi);
        lg[o] = lo + hi + bsh[o];
        m = fmaxf(m, lg[o]);
    }
    float s = 0.f;
#pragma unroll
    for (int o = 0; o < 10; o++) s += __expf(lg[o] - m);
    float lse = m + __logf(s);

    float* op = out + (size_t)(gbase + lane) * 10;
#pragma unroll
    for (int o = 0; o < 10; o += 2) {
        *(float2*)(op + o) = make_float2(lg[o] - lse, lg[o + 1] - lse);
    }
}

extern "C" void kernel_launch(void* const* d_in, const int* in_sizes, int n_in,
                              void* d_out, int out_size) {
    const float* x = (const float*)d_in[0];   // (B,1,28,28) fp32
    const float* W = (const float*)d_in[1];   // (10,784)    fp32
    const float* b = (const float*)d_in[2];   // (10,)       fp32
    float* out = (float*)d_out;               // (B,10)      fp32

    int batch = in_sizes[0] / 784;
    int grid = (batch + IMG_PER_BLOCK - 1) / IMG_PER_BLOCK;

    cudaFuncSetAttribute(quanv_kernel,
                         cudaFuncAttributeMaxDynamicSharedMemorySize, SMEM_BYTES);
    quanv_kernel<<<grid, THREADS, SMEM_BYTES>>>(x, W, b, out, batch);
}